// round 15
// baseline (speedup 1.0000x reference)
#include <cuda_runtime.h>
#include <cuda_fp16.h>
#include <math.h>

// Problem constants
#define BB   32
#define CC   256
#define HIN  30
#define OH   28
#define PPB  784
#define NPIX 25088
#define NK   2048
#define BOWOFF (BB*NK)

// Pass-1 tiling (tensor-core)
#define BM 64              // pixels per block
#define BN 256             // codes per tile
#define KC 16              // k-chunk (halves)
#define NTILE 8            // global code tiles
#define HTILE 4            // tiles per half-block
#define NSTAGE (HTILE*32)  // 128 stages per block: 16 chunks x {hi,lo} per tile
#define ASTR 272           // A smem row stride (halves)
#define BSTR 16            // B smem row stride (halves) — 32B rows, conflict-free
#define SLOT_HALVES (BN*BSTR)   // 4096 halves = 8KB per slot

// smem byte offsets (total ~104 KB -> 2 blocks/SM)
#define OFF_AL   34816
#define OFF_B    69632          // 4 slots x 8KB = 32KB
#define OFF_F2   102400
#define OFF_E2   102656
#define OFF_MN   103680
#define OFF_MR   103936
#define OFF_SR   104192
#define OFF_MP   104448
#define OFF_SP   105472
#define SMEM1_BYTES 106496

// Pass-2: codes per block
#define P2K 64

// Scratch
__device__ float g_e2[NK];
__device__ float g_pixmax[2*NPIX];   // [half][pix]
__device__ float g_pixsum[2*NPIX];
__device__ float g_mtile[NTILE*NPIX];
__device__ float g_bow[BB*NK];
// fp16 staged exp(l - m_tile), code-pair interleaved: [b][kpair][pix]{2 codes}
__device__ __align__(16) __half2 g_stage[(size_t)(NK/2)*NPIX];
__device__ __align__(16) __half g_ehiP[NK*CC];  // k-permuted fp16 hi split
__device__ __align__(16) __half g_eloP[NK*CC];  // k-permuted fp16 lo split

// ---------------------------------------------------------------------------
__device__ __forceinline__ void mma16816(float* c, const unsigned* a,
                                         unsigned b0, unsigned b1) {
    asm volatile(
        "mma.sync.aligned.m16n8k16.row.col.f32.f16.f16.f32 "
        "{%0,%1,%2,%3}, {%4,%5,%6,%7}, {%8,%9}, {%0,%1,%2,%3};"
        : "+f"(c[0]), "+f"(c[1]), "+f"(c[2]), "+f"(c[3])
        : "r"(a[0]), "r"(a[1]), "r"(a[2]), "r"(a[3]), "r"(b0), "r"(b1));
}

// ---------------------------------------------------------------------------
// Prep: fused e2 + fp16 hi/lo split (k-permuted). Block = 2 codebook rows.
// ---------------------------------------------------------------------------
__global__ __launch_bounds__(256)
void prep_kernel(const float* __restrict__ emb) {
    __shared__ float red[8];
    const int tid = threadIdx.x;
    const int idx = blockIdx.x * 256 + tid;       // pair index
    const int k  = idx >> 7;
    const int cp = idx & 127;
    float v0 = emb[k*CC + 2*cp];
    float v1 = emb[k*CC + 2*cp + 1];
    __half h0 = __float2half_rn(v0), h1 = __float2half_rn(v1);
    __half l0 = __float2half_rn(v0 - __half2float(h0));
    __half l1 = __float2half_rn(v1 - __half2float(h1));
    int jp = cp & 7, grp = cp >> 3;
    int phys = grp*16 + (((jp & 3) << 1) + (jp >> 2)) * 2;
    *(__half2*)&g_ehiP[(size_t)k*CC + phys] = __halves2half2(h0, h1);
    *(__half2*)&g_eloP[(size_t)k*CC + phys] = __halves2half2(l0, l1);

    float p2 = v0*v0 + v1*v1;
    #pragma unroll
    for (int o = 16; o; o >>= 1) p2 += __shfl_xor_sync(0xffffffffu, p2, o);
    if ((tid & 31) == 0) red[tid >> 5] = p2;
    __syncthreads();
    if ((tid & 127) == 0) {
        int w0 = (tid >> 7) * 4;
        g_e2[k] = red[w0] + red[w0+1] + red[w0+2] + red[w0+3];
    }
}

// ---------------------------------------------------------------------------
// Pass 1: 64 pixels x 1024 codes (half the codebook) per block; 1568 blocks.
// fp16-split HMMA, occ=2, 4-slot cp.async ring (prefetch distance 3).
// Epilogue stages exp(l - m_tile) as packed __half2 code pairs (32B-sector
// coalesced); per-half (m,s) to global.
// ---------------------------------------------------------------------------
extern __shared__ float smem1[];

__global__ __launch_bounds__(256, 2)
void pass1_kernel(const float* __restrict__ feat,
                  const float* __restrict__ md,
                  float* __restrict__ out)
{
    char* smem_raw = (char*)smem1;
    __half* Ah    = (__half*)smem_raw;               // [64][272]
    __half* Al    = (__half*)(smem_raw + OFF_AL);    // [64][272]
    __half* Bbuf  = (__half*)(smem_raw + OFF_B);     // 4 x [256][16]
    float*  f2s   = (float*)(smem_raw + OFF_F2);     // 64
    float*  e2s   = (float*)(smem_raw + OFF_E2);     // 256
    float*  mnew  = (float*)(smem_raw + OFF_MN);     // 64
    float*  m_run = (float*)(smem_raw + OFF_MR);     // 64
    float*  s_run = (float*)(smem_raw + OFF_SR);     // 64
    float*  mpart = (float*)(smem_raw + OFF_MP);     // 4 x 64
    float*  spart = (float*)(smem_raw + OFF_SP);     // 4 x 64
    float*  red   = mpart;                           // alias (prologue only)

    const int tid  = threadIdx.x;
    const int warp = tid >> 5;
    const int lane = tid & 31;
    const int wm = warp >> 2;        // 0..1
    const int wn = warp & 3;         // 0..3
    const int tq = lane >> 2;        // 0..7
    const int tr = lane & 3;         // 0..3
    const int half = blockIdx.x & 1;
    const int gp0  = (blockIdx.x >> 1) * BM;
    const int tileBase = half * HTILE;
    const int phase = ((blockIdx.x >> 1) & 1) * 2;
    const float alpha  = 15.0f / md[0];
    const float alpha2 = 2.0f * alpha;

    auto tile_of = [&](int s) {
        return tileBase + (((s >> 5) + phase) & (HTILE - 1));
    };

    // ---- one 8KB B chunk via cp.async (2 x 16B per thread) ----
    auto issue = [&](int s) {
        int tile = tile_of(s), sub = s & 31;
        int chunk = sub >> 1, split = sub & 1;
        const __half* src = (split ? g_eloP : g_ehiP)
                          + (size_t)tile*BN*CC + chunk*KC;
        __half* dstB = Bbuf + (size_t)(s & 3)*SLOT_HALVES;
        #pragma unroll
        for (int it = 0; it < 2; ++it) {
            int lin = it*256 + tid;
            int row = lin >> 1, seg = lin & 1;
            const __half* sp = src + (size_t)row*CC + seg*8;
            unsigned d = (unsigned)__cvta_generic_to_shared(dstB + row*BSTR + seg*8);
            asm volatile("cp.async.cg.shared.global [%0], [%1], 16;"
                         :: "r"(d), "l"(sp) : "memory");
        }
        asm volatile("cp.async.commit_group;" ::: "memory");
    };

    issue(0); issue(1); issue(2);   // prefetch distance 3

    // ---- load + split features, accumulate f2 ----
    {
        int p  = tid & 63;
        int q4 = tid >> 6;
        int gp = gp0 + p;
        int b  = gp / PPB;
        int r  = gp - b*PPB;
        int h  = r / OH, w = r - h*OH;
        const float* fb = feat + (size_t)b*CC*HIN*HIN + (h+1)*HIN + (w+1);
        float p2 = 0.f;
        for (int cp = q4; cp < 128; cp += 4) {
            float v0 = fb[(2*cp)*HIN*HIN];
            float v1 = fb[(2*cp+1)*HIN*HIN];
            p2 += v0*v0 + v1*v1;
            __half h0 = __float2half_rn(v0), h1 = __float2half_rn(v1);
            __half l0 = __float2half_rn(v0 - __half2float(h0));
            __half l1 = __float2half_rn(v1 - __half2float(h1));
            int jp = cp & 7, grp = cp >> 3;
            int phys = grp*16 + (((jp & 3) << 1) + (jp >> 2)) * 2;
            *(__half2*)&Ah[p*ASTR + phys] = __halves2half2(h0, h1);
            *(__half2*)&Al[p*ASTR + phys] = __halves2half2(l0, l1);
        }
        red[q4*64 + p] = p2;
    }
    __syncthreads();
    if (tid < 64) {
        f2s[tid]   = -alpha * (red[tid] + red[64+tid] + red[128+tid] + red[192+tid]);
        m_run[tid] = -1e30f;
        s_run[tid] = 0.f;
    }

    float acc[2][8][4];

    for (int s = 0; s < NSTAGE; ++s) {
        const int tile  = tile_of(s);
        const int sub   = s & 31;
        const int chunk = sub >> 1;
        const int split = sub & 1;

        asm volatile("cp.async.wait_group 2;" ::: "memory");
        __syncthreads();

        if (sub == 0) {
            #pragma unroll
            for (int mt = 0; mt < 2; ++mt)
                #pragma unroll
                for (int nt = 0; nt < 8; ++nt)
                    #pragma unroll
                    for (int i = 0; i < 4; ++i) acc[mt][nt][i] = 0.f;
            e2s[tid] = -alpha * g_e2[tile*BN + tid];
        }
        if (s + 3 < NSTAGE) issue(s + 3);
        else asm volatile("cp.async.commit_group;" ::: "memory");

        // ---- mma on slot s&3: hi -> (Ah+Al)·Bhi shared z; lo -> Ah·Blo ----
        const __half* B = Bbuf + (size_t)(s & 3)*SLOT_HALVES;
        const int kc = chunk * KC;
        {
            uint2 z[8];
            #pragma unroll
            for (int nt = 0; nt < 8; ++nt)
                z[nt] = *(const uint2*)&B[(wn*64 + nt*8 + tq)*BSTR + 4*tr];

            unsigned afrH[2][4];
            #pragma unroll
            for (int mt = 0; mt < 2; ++mt) {
                int row = wm*32 + mt*16 + tq;
                uint2 x = *(const uint2*)&Ah[row*ASTR + kc + 4*tr];
                uint2 y = *(const uint2*)&Ah[(row+8)*ASTR + kc + 4*tr];
                afrH[mt][0] = x.x; afrH[mt][1] = y.x;
                afrH[mt][2] = x.y; afrH[mt][3] = y.y;
            }
            #pragma unroll
            for (int nt = 0; nt < 8; ++nt) {
                mma16816(acc[0][nt], afrH[0], z[nt].x, z[nt].y);
                mma16816(acc[1][nt], afrH[1], z[nt].x, z[nt].y);
            }
            if (split == 0) {
                unsigned afrL[2][4];
                #pragma unroll
                for (int mt = 0; mt < 2; ++mt) {
                    int row = wm*32 + mt*16 + tq;
                    uint2 x = *(const uint2*)&Al[row*ASTR + kc + 4*tr];
                    uint2 y = *(const uint2*)&Al[(row+8)*ASTR + kc + 4*tr];
                    afrL[mt][0] = x.x; afrL[mt][1] = y.x;
                    afrL[mt][2] = x.y; afrL[mt][3] = y.y;
                }
                #pragma unroll
                for (int nt = 0; nt < 8; ++nt) {
                    mma16816(acc[0][nt], afrL[0], z[nt].x, z[nt].y);
                    mma16816(acc[1][nt], afrL[1], z[nt].x, z[nt].y);
                }
            }
        }

        // ---- register epilogue at last chunk of tile ----
        if (sub == 31) {
            float rmax[4];
            #pragma unroll
            for (int i = 0; i < 4; ++i) rmax[i] = -1e30f;
            #pragma unroll
            for (int mt = 0; mt < 2; ++mt) {
                int r0 = wm*32 + mt*16 + tq;
                float fa = f2s[r0], fb2 = f2s[r0 + 8];
                #pragma unroll
                for (int nt = 0; nt < 8; ++nt) {
                    int n0 = wn*64 + nt*8 + 2*tr;
                    float e0 = e2s[n0], e1 = e2s[n0 + 1];
                    float l0 = fmaf(alpha2, acc[mt][nt][0], fa  + e0);
                    float l1 = fmaf(alpha2, acc[mt][nt][1], fa  + e1);
                    float l2 = fmaf(alpha2, acc[mt][nt][2], fb2 + e0);
                    float l3 = fmaf(alpha2, acc[mt][nt][3], fb2 + e1);
                    acc[mt][nt][0] = l0; acc[mt][nt][1] = l1;
                    acc[mt][nt][2] = l2; acc[mt][nt][3] = l3;
                    rmax[2*mt]   = fmaxf(rmax[2*mt],   fmaxf(l0, l1));
                    rmax[2*mt+1] = fmaxf(rmax[2*mt+1], fmaxf(l2, l3));
                }
            }
            #pragma unroll
            for (int i = 0; i < 4; ++i) {
                rmax[i] = fmaxf(rmax[i], __shfl_xor_sync(0xffffffffu, rmax[i], 1));
                rmax[i] = fmaxf(rmax[i], __shfl_xor_sync(0xffffffffu, rmax[i], 2));
            }
            if (tr == 0) {
                #pragma unroll
                for (int i = 0; i < 4; ++i) {
                    int row = wm*32 + (i >> 1)*16 + tq + (i & 1)*8;
                    mpart[wn*64 + row] = rmax[i];
                }
            }
            __syncthreads();
            if (tid < 64) {
                float mm = fmaxf(fmaxf(mpart[tid], mpart[64 + tid]),
                                 fmaxf(mpart[128 + tid], mpart[192 + tid]));
                mnew[tid] = fmaxf(mm, m_run[tid]);
            }
            __syncthreads();

            // exp sums + packed fp16 staging stores (code pairs, 32B sectors)
            float rsum[4];
            #pragma unroll
            for (int i = 0; i < 4; ++i) rsum[i] = 0.f;
            #pragma unroll
            for (int mt = 0; mt < 2; ++mt) {
                int r0 = wm*32 + mt*16 + tq;
                int r1 = r0 + 8;
                int gpa = gp0 + r0, gpb = gp0 + r1;
                int ba = gpa / PPB, bb2 = gpb / PPB;
                size_t base0 = (size_t)ba*(NK/2)*PPB + (gpa - ba*PPB);
                size_t base1 = (size_t)bb2*(NK/2)*PPB + (gpb - bb2*PPB);
                float mn0 = mnew[r0], mn1 = mnew[r1];
                #pragma unroll
                for (int nt = 0; nt < 8; ++nt) {
                    int kp = tile*(BN/2) + wn*32 + nt*4 + tr;   // code pair
                    float e00 = __expf(acc[mt][nt][0] - mn0);
                    float e01 = __expf(acc[mt][nt][1] - mn0);
                    float e10 = __expf(acc[mt][nt][2] - mn1);
                    float e11 = __expf(acc[mt][nt][3] - mn1);
                    rsum[2*mt]   += e00 + e01;
                    rsum[2*mt+1] += e10 + e11;
                    g_stage[base0 + (size_t)kp*PPB] =
                        __halves2half2(__float2half_rn(e00), __float2half_rn(e01));
                    g_stage[base1 + (size_t)kp*PPB] =
                        __halves2half2(__float2half_rn(e10), __float2half_rn(e11));
                }
            }
            #pragma unroll
            for (int i = 0; i < 4; ++i) {
                rsum[i] += __shfl_xor_sync(0xffffffffu, rsum[i], 1);
                rsum[i] += __shfl_xor_sync(0xffffffffu, rsum[i], 2);
            }
            if (tr == 0) {
                #pragma unroll
                for (int i = 0; i < 4; ++i) {
                    int row = wm*32 + (i >> 1)*16 + tq + (i & 1)*8;
                    spart[wn*64 + row] = rsum[i];
                }
            }
            __syncthreads();
            if (tid < 64) {
                float ss = spart[tid] + spart[64 + tid]
                         + spart[128 + tid] + spart[192 + tid];
                s_run[tid] = s_run[tid]*__expf(m_run[tid] - mnew[tid]) + ss;
                m_run[tid] = mnew[tid];
                g_mtile[tile*NPIX + gp0 + tid] = mnew[tid];
            }
        }
    }

    __syncthreads();
    if (tid < 64) {
        g_pixmax[half*NPIX + gp0 + tid] = m_run[tid];
        g_pixsum[half*NPIX + gp0 + tid] = s_run[tid];
    }
    (void)out;
}

// ---------------------------------------------------------------------------
// Pass 2: merge half-softmax states per pixel, then
// codes[2kp][pix]   = lo(stage[kp][pix]) * fac[pix]
// codes[2kp+1][pix] = hi(stage[kp][pix]) * fac[pix]
// 64 codes (32 pairs) per block; warp handles 4 pairs. Pure stream, no RMW.
// ---------------------------------------------------------------------------
__global__ __launch_bounds__(256)
void pass2_kernel(float* __restrict__ out) {
    __shared__ __align__(16) float fac[PPB];

    const int b    = blockIdx.x >> 5;         // 32 blocks per batch
    const int k0   = (blockIdx.x & 31) * P2K;
    const int tile = k0 >> 8;                 // 256-code tiles (P2K=64 divides)
    const int tid  = threadIdx.x;

    for (int t = tid; t < PPB; t += 256) {
        int pix = b*PPB + t;
        float m0 = g_pixmax[pix],        m1 = g_pixmax[NPIX + pix];
        float s0 = g_pixsum[pix],        s1 = g_pixsum[NPIX + pix];
        float mf = fmaxf(m0, m1);
        float sf = s0*__expf(m0 - mf) + s1*__expf(m1 - mf);
        float mt = g_mtile[tile*NPIX + pix];
        fac[t] = __expf(mt - mf) * __frcp_rn(sf);
    }
    __syncthreads();

    const int w = tid >> 5, lane = tid & 31;

    #pragma unroll
    for (int kk = 0; kk < P2K/16; ++kk) {     // 4 code pairs per warp
        const int kp = (k0 >> 1) + w*(P2K/16) + kk;
        const __half2* sp = g_stage + (size_t)(b*(NK/2) + kp)*PPB;
        float* o0 = out + (size_t)BOWOFF + ((size_t)b*NK + 2*kp)*PPB;
        float* o1 = o0 + PPB;
        float a0 = 0.f, a1 = 0.f;
        for (int t = lane; t < PPB; t += 32) {
            float2 v = __half22float2(sp[t]);
            float f = fac[t];
            float x0 = v.x * f, x1 = v.y * f;
            o0[t] = x0; o1[t] = x1;
            a0 += x0; a1 += x1;
        }
        #pragma unroll
        for (int o = 16; o; o >>= 1) {
            a0 += __shfl_xor_sync(0xffffffffu, a0, o);
            a1 += __shfl_xor_sync(0xffffffffu, a1, o);
        }
        if (lane == 0) {
            g_bow[b*NK + 2*kp]     = a0;
            g_bow[b*NK + 2*kp + 1] = a1;
        }
    }
}

// ---------------------------------------------------------------------------
// Pass 3: bow normalize (1024 threads, 2 codes/thread)
// ---------------------------------------------------------------------------
__global__ __launch_bounds__(1024)
void pass3_kernel(float* __restrict__ out) {
    __shared__ float redw[32];
    __shared__ float denom_s;
    const int b   = blockIdx.x;
    const int tid = threadIdx.x;
    const float invP = 1.0f / (float)PPB;

    float v0 = g_bow[b*NK + tid]        * invP;
    float v1 = g_bow[b*NK + tid + 1024] * invP;
    float acc = v0 + v1;
    #pragma unroll
    for (int o = 16; o; o >>= 1) acc += __shfl_xor_sync(0xffffffffu, acc, o);
    if ((tid & 31) == 0) redw[tid >> 5] = acc;
    __syncthreads();
    if (tid < 32) {
        float t = redw[tid];
        #pragma unroll
        for (int o = 16; o; o >>= 1) t += __shfl_xor_sync(0xffffffffu, t, o);
        if (tid == 0) denom_s = fmaxf(t, 1e-12f);
    }
    __syncthreads();
    const float inv = __frcp_rn(denom_s);
    out[b*NK + tid]        = v0 * inv;
    out[b*NK + tid + 1024] = v1 * inv;
}

// ---------------------------------------------------------------------------
extern "C" void kernel_launch(void* const* d_in, const int* in_sizes, int n_in,
                              void* d_out, int out_size) {
    const float* feat = (const float*)d_in[0];   // (32,256,30,30)
    const float* emb  = (const float*)d_in[1];   // (2048,256)
    const float* md   = (const float*)d_in[2];   // (1,)
    float* out = (float*)d_out;

    cudaFuncSetAttribute(pass1_kernel,
                         cudaFuncAttributeMaxDynamicSharedMemorySize, SMEM1_BYTES);

    prep_kernel <<<NK/2, 256>>>(emb);
    pass1_kernel<<<(NPIX/BM)*2, 256, SMEM1_BYTES>>>(feat, md, out);
    pass2_kernel<<<BB*NK/P2K, 256>>>(out);
    pass3_kernel<<<BB, 1024>>>(out);
    (void)in_sizes; (void)n_in; (void)out_size;
}

// round 16
// speedup vs baseline: 1.0452x; 1.0452x over previous
#include <cuda_runtime.h>
#include <cuda_fp16.h>
#include <math.h>

// Problem constants
#define BB   32
#define CC   256
#define HIN  30
#define OH   28
#define PPB  784
#define NPIX 25088
#define NK   2048
#define BOWOFF (BB*NK)

// Pass-1 tiling (tensor-core)
#define BM 64              // pixels per block
#define BN 256             // codes per tile
#define KC 16              // k-chunk (halves)
#define NTILE 8            // global code tiles
#define HTILE 4            // tiles per half-block
#define NSTAGE (HTILE*32)  // 128 stages per block: 16 chunks x {hi,lo} per tile
#define ASTR 272           // A smem row stride (halves)
#define BSTR 16            // B smem row stride (halves) — 32B rows, conflict-free
#define SLOT_HALVES (BN*BSTR)   // 4096 halves = 8KB per slot

// smem byte offsets (total ~104 KB -> 2 blocks/SM)
#define OFF_AL   34816
#define OFF_B    69632          // 4 slots x 8KB = 32KB
#define OFF_F2   102400
#define OFF_E2   102656
#define OFF_MN   103680
#define OFF_MR   103936
#define OFF_SR   104192
#define OFF_MP   104448
#define OFF_SP   105472
#define SMEM1_BYTES 106496

// Pass-2: codes per block
#define P2K 64

// Scratch
__device__ float g_e2[NK];
__device__ float g_pixmax[2*NPIX];   // [half][pix]
__device__ float g_pixsum[2*NPIX];
__device__ float g_mtile[NTILE*NPIX];
__device__ float g_bow[BB*NK];
__device__ __align__(16) __half g_ehiP[NK*CC];  // k-permuted fp16 hi split
__device__ __align__(16) __half g_eloP[NK*CC];  // k-permuted fp16 lo split

// ---------------------------------------------------------------------------
__device__ __forceinline__ void mma16816(float* c, const unsigned* a,
                                         unsigned b0, unsigned b1) {
    asm volatile(
        "mma.sync.aligned.m16n8k16.row.col.f32.f16.f16.f32 "
        "{%0,%1,%2,%3}, {%4,%5,%6,%7}, {%8,%9}, {%0,%1,%2,%3};"
        : "+f"(c[0]), "+f"(c[1]), "+f"(c[2]), "+f"(c[3])
        : "r"(a[0]), "r"(a[1]), "r"(a[2]), "r"(a[3]), "r"(b0), "r"(b1));
}

// ---------------------------------------------------------------------------
// Prep: fused e2 + fp16 hi/lo split (k-permuted). Block = 2 codebook rows.
// ---------------------------------------------------------------------------
__global__ __launch_bounds__(256)
void prep_kernel(const float* __restrict__ emb) {
    __shared__ float red[8];
    const int tid = threadIdx.x;
    const int idx = blockIdx.x * 256 + tid;       // pair index
    const int k  = idx >> 7;
    const int cp = idx & 127;
    float v0 = emb[k*CC + 2*cp];
    float v1 = emb[k*CC + 2*cp + 1];
    __half h0 = __float2half_rn(v0), h1 = __float2half_rn(v1);
    __half l0 = __float2half_rn(v0 - __half2float(h0));
    __half l1 = __float2half_rn(v1 - __half2float(h1));
    int jp = cp & 7, grp = cp >> 3;
    int phys = grp*16 + (((jp & 3) << 1) + (jp >> 2)) * 2;
    *(__half2*)&g_ehiP[(size_t)k*CC + phys] = __halves2half2(h0, h1);
    *(__half2*)&g_eloP[(size_t)k*CC + phys] = __halves2half2(l0, l1);

    float p2 = v0*v0 + v1*v1;
    #pragma unroll
    for (int o = 16; o; o >>= 1) p2 += __shfl_xor_sync(0xffffffffu, p2, o);
    if ((tid & 31) == 0) red[tid >> 5] = p2;
    __syncthreads();
    if ((tid & 127) == 0) {
        int w0 = (tid >> 7) * 4;
        g_e2[k] = red[w0] + red[w0+1] + red[w0+2] + red[w0+3];
    }
}

// ---------------------------------------------------------------------------
// Pass 1: 64 pixels x 1024 codes (half the codebook) per block; 1568 blocks.
// fp16-split HMMA, occ=2, 4-slot cp.async ring (prefetch distance 3).
// Tile order rotated per-block so co-resident blocks' epilogues interleave.
// Epilogue stores exp(l - m_tile) fp32; per-half (m,s) to global.
// ---------------------------------------------------------------------------
extern __shared__ float smem1[];

__global__ __launch_bounds__(256, 2)
void pass1_kernel(const float* __restrict__ feat,
                  const float* __restrict__ md,
                  float* __restrict__ out)
{
    char* smem_raw = (char*)smem1;
    __half* Ah    = (__half*)smem_raw;               // [64][272]
    __half* Al    = (__half*)(smem_raw + OFF_AL);    // [64][272]
    __half* Bbuf  = (__half*)(smem_raw + OFF_B);     // 4 x [256][16]
    float*  f2s   = (float*)(smem_raw + OFF_F2);     // 64
    float*  e2s   = (float*)(smem_raw + OFF_E2);     // 256
    float*  mnew  = (float*)(smem_raw + OFF_MN);     // 64
    float*  m_run = (float*)(smem_raw + OFF_MR);     // 64
    float*  s_run = (float*)(smem_raw + OFF_SR);     // 64
    float*  mpart = (float*)(smem_raw + OFF_MP);     // 4 x 64
    float*  spart = (float*)(smem_raw + OFF_SP);     // 4 x 64
    float*  red   = mpart;                           // alias (prologue only)

    const int tid  = threadIdx.x;
    const int warp = tid >> 5;
    const int lane = tid & 31;
    const int wm = warp >> 2;        // 0..1
    const int wn = warp & 3;         // 0..3
    const int tq = lane >> 2;        // 0..7
    const int tr = lane & 3;         // 0..3
    const int half = blockIdx.x & 1;
    const int gp0  = (blockIdx.x >> 1) * BM;
    const int tileBase = half * HTILE;
    const int phase = ((blockIdx.x >> 1) & 1) * 2;
    const float alpha  = 15.0f / md[0];
    const float alpha2 = 2.0f * alpha;

    auto tile_of = [&](int s) {
        return tileBase + (((s >> 5) + phase) & (HTILE - 1));
    };

    // ---- one 8KB B chunk via cp.async (2 x 16B per thread) ----
    auto issue = [&](int s) {
        int tile = tile_of(s), sub = s & 31;
        int chunk = sub >> 1, split = sub & 1;
        const __half* src = (split ? g_eloP : g_ehiP)
                          + (size_t)tile*BN*CC + chunk*KC;
        __half* dstB = Bbuf + (size_t)(s & 3)*SLOT_HALVES;
        #pragma unroll
        for (int it = 0; it < 2; ++it) {
            int lin = it*256 + tid;
            int row = lin >> 1, seg = lin & 1;
            const __half* sp = src + (size_t)row*CC + seg*8;
            unsigned d = (unsigned)__cvta_generic_to_shared(dstB + row*BSTR + seg*8);
            asm volatile("cp.async.cg.shared.global [%0], [%1], 16;"
                         :: "r"(d), "l"(sp) : "memory");
        }
        asm volatile("cp.async.commit_group;" ::: "memory");
    };

    issue(0); issue(1); issue(2);   // prefetch distance 3

    // ---- load + split features, accumulate f2 ----
    {
        int p  = tid & 63;
        int q4 = tid >> 6;
        int gp = gp0 + p;
        int b  = gp / PPB;
        int r  = gp - b*PPB;
        int h  = r / OH, w = r - h*OH;
        const float* fb = feat + (size_t)b*CC*HIN*HIN + (h+1)*HIN + (w+1);
        float p2 = 0.f;
        for (int cp = q4; cp < 128; cp += 4) {
            float v0 = fb[(2*cp)*HIN*HIN];
            float v1 = fb[(2*cp+1)*HIN*HIN];
            p2 += v0*v0 + v1*v1;
            __half h0 = __float2half_rn(v0), h1 = __float2half_rn(v1);
            __half l0 = __float2half_rn(v0 - __half2float(h0));
            __half l1 = __float2half_rn(v1 - __half2float(h1));
            int jp = cp & 7, grp = cp >> 3;
            int phys = grp*16 + (((jp & 3) << 1) + (jp >> 2)) * 2;
            *(__half2*)&Ah[p*ASTR + phys] = __halves2half2(h0, h1);
            *(__half2*)&Al[p*ASTR + phys] = __halves2half2(l0, l1);
        }
        red[q4*64 + p] = p2;
    }
    __syncthreads();
    if (tid < 64) {
        f2s[tid]   = -alpha * (red[tid] + red[64+tid] + red[128+tid] + red[192+tid]);
        m_run[tid] = -1e30f;
        s_run[tid] = 0.f;
    }

    float acc[2][8][4];

    for (int s = 0; s < NSTAGE; ++s) {
        const int tile  = tile_of(s);
        const int sub   = s & 31;
        const int chunk = sub >> 1;
        const int split = sub & 1;

        asm volatile("cp.async.wait_group 2;" ::: "memory");
        __syncthreads();

        if (sub == 0) {
            #pragma unroll
            for (int mt = 0; mt < 2; ++mt)
                #pragma unroll
                for (int nt = 0; nt < 8; ++nt)
                    #pragma unroll
                    for (int i = 0; i < 4; ++i) acc[mt][nt][i] = 0.f;
            e2s[tid] = -alpha * g_e2[tile*BN + tid];
        }
        if (s + 3 < NSTAGE) issue(s + 3);
        else asm volatile("cp.async.commit_group;" ::: "memory");

        // ---- mma on slot s&3: hi -> (Ah+Al)·Bhi shared z; lo -> Ah·Blo ----
        const __half* B = Bbuf + (size_t)(s & 3)*SLOT_HALVES;
        const int kc = chunk * KC;
        {
            uint2 z[8];
            #pragma unroll
            for (int nt = 0; nt < 8; ++nt)
                z[nt] = *(const uint2*)&B[(wn*64 + nt*8 + tq)*BSTR + 4*tr];

            unsigned afrH[2][4];
            #pragma unroll
            for (int mt = 0; mt < 2; ++mt) {
                int row = wm*32 + mt*16 + tq;
                uint2 x = *(const uint2*)&Ah[row*ASTR + kc + 4*tr];
                uint2 y = *(const uint2*)&Ah[(row+8)*ASTR + kc + 4*tr];
                afrH[mt][0] = x.x; afrH[mt][1] = y.x;
                afrH[mt][2] = x.y; afrH[mt][3] = y.y;
            }
            #pragma unroll
            for (int nt = 0; nt < 8; ++nt) {
                mma16816(acc[0][nt], afrH[0], z[nt].x, z[nt].y);
                mma16816(acc[1][nt], afrH[1], z[nt].x, z[nt].y);
            }
            if (split == 0) {
                unsigned afrL[2][4];
                #pragma unroll
                for (int mt = 0; mt < 2; ++mt) {
                    int row = wm*32 + mt*16 + tq;
                    uint2 x = *(const uint2*)&Al[row*ASTR + kc + 4*tr];
                    uint2 y = *(const uint2*)&Al[(row+8)*ASTR + kc + 4*tr];
                    afrL[mt][0] = x.x; afrL[mt][1] = y.x;
                    afrL[mt][2] = x.y; afrL[mt][3] = y.y;
                }
                #pragma unroll
                for (int nt = 0; nt < 8; ++nt) {
                    mma16816(acc[0][nt], afrL[0], z[nt].x, z[nt].y);
                    mma16816(acc[1][nt], afrL[1], z[nt].x, z[nt].y);
                }
            }
        }

        // ---- register epilogue at last chunk of tile ----
        if (sub == 31) {
            float rmax[4];
            #pragma unroll
            for (int i = 0; i < 4; ++i) rmax[i] = -1e30f;
            #pragma unroll
            for (int mt = 0; mt < 2; ++mt) {
                int r0 = wm*32 + mt*16 + tq;
                float fa = f2s[r0], fb2 = f2s[r0 + 8];
                #pragma unroll
                for (int nt = 0; nt < 8; ++nt) {
                    int n0 = wn*64 + nt*8 + 2*tr;
                    float e0 = e2s[n0], e1 = e2s[n0 + 1];
                    float l0 = fmaf(alpha2, acc[mt][nt][0], fa  + e0);
                    float l1 = fmaf(alpha2, acc[mt][nt][1], fa  + e1);
                    float l2 = fmaf(alpha2, acc[mt][nt][2], fb2 + e0);
                    float l3 = fmaf(alpha2, acc[mt][nt][3], fb2 + e1);
                    acc[mt][nt][0] = l0; acc[mt][nt][1] = l1;
                    acc[mt][nt][2] = l2; acc[mt][nt][3] = l3;
                    rmax[2*mt]   = fmaxf(rmax[2*mt],   fmaxf(l0, l1));
                    rmax[2*mt+1] = fmaxf(rmax[2*mt+1], fmaxf(l2, l3));
                }
            }
            #pragma unroll
            for (int i = 0; i < 4; ++i) {
                rmax[i] = fmaxf(rmax[i], __shfl_xor_sync(0xffffffffu, rmax[i], 1));
                rmax[i] = fmaxf(rmax[i], __shfl_xor_sync(0xffffffffu, rmax[i], 2));
            }
            if (tr == 0) {
                #pragma unroll
                for (int i = 0; i < 4; ++i) {
                    int row = wm*32 + (i >> 1)*16 + tq + (i & 1)*8;
                    mpart[wn*64 + row] = rmax[i];
                }
            }
            __syncthreads();
            if (tid < 64) {
                float mm = fmaxf(fmaxf(mpart[tid], mpart[64 + tid]),
                                 fmaxf(mpart[128 + tid], mpart[192 + tid]));
                mnew[tid] = fmaxf(mm, m_run[tid]);
            }
            __syncthreads();

            // exp sums + store exp(l - m_tile) directly (fp32)
            float rsum[4];
            #pragma unroll
            for (int i = 0; i < 4; ++i) rsum[i] = 0.f;
            #pragma unroll
            for (int mt = 0; mt < 2; ++mt) {
                int r0 = wm*32 + mt*16 + tq;
                int r1 = r0 + 8;
                int gpa = gp0 + r0, gpb = gp0 + r1;
                int ba = gpa / PPB, bb2 = gpb / PPB;
                size_t base0 = (size_t)BOWOFF + (size_t)ba*NK*PPB + (gpa - ba*PPB);
                size_t base1 = (size_t)BOWOFF + (size_t)bb2*NK*PPB + (gpb - bb2*PPB);
                float mn0 = mnew[r0], mn1 = mnew[r1];
                #pragma unroll
                for (int nt = 0; nt < 8; ++nt) {
                    int ng = tile*BN + wn*64 + nt*8 + 2*tr;
                    float e00 = __expf(acc[mt][nt][0] - mn0);
                    float e01 = __expf(acc[mt][nt][1] - mn0);
                    float e10 = __expf(acc[mt][nt][2] - mn1);
                    float e11 = __expf(acc[mt][nt][3] - mn1);
                    rsum[2*mt]   += e00 + e01;
                    rsum[2*mt+1] += e10 + e11;
                    out[base0 + (size_t)ng*PPB]     = e00;
                    out[base0 + (size_t)(ng+1)*PPB] = e01;
                    out[base1 + (size_t)ng*PPB]     = e10;
                    out[base1 + (size_t)(ng+1)*PPB] = e11;
                }
            }
            #pragma unroll
            for (int i = 0; i < 4; ++i) {
                rsum[i] += __shfl_xor_sync(0xffffffffu, rsum[i], 1);
                rsum[i] += __shfl_xor_sync(0xffffffffu, rsum[i], 2);
            }
            if (tr == 0) {
                #pragma unroll
                for (int i = 0; i < 4; ++i) {
                    int row = wm*32 + (i >> 1)*16 + tq + (i & 1)*8;
                    spart[wn*64 + row] = rsum[i];
                }
            }
            __syncthreads();
            if (tid < 64) {
                float ss = spart[tid] + spart[64 + tid]
                         + spart[128 + tid] + spart[192 + tid];
                s_run[tid] = s_run[tid]*__expf(m_run[tid] - mnew[tid]) + ss;
                m_run[tid] = mnew[tid];
                g_mtile[tile*NPIX + gp0 + tid] = mnew[tid];
            }
        }
    }

    __syncthreads();
    if (tid < 64) {
        g_pixmax[half*NPIX + gp0 + tid] = m_run[tid];
        g_pixsum[half*NPIX + gp0 + tid] = s_run[tid];
    }
}

// ---------------------------------------------------------------------------
// Pass 2: merge the two half-softmax states per pixel, then
// codes *= exp(m_tile - m_fin)/s_fin. 64 codes per block (fac amortized 8x);
// one warp handles 8 codes sequentially. Cache-streaming (evict-first) hints
// on the 410MB RMW stream to avoid L2 pollution.
// ---------------------------------------------------------------------------
__global__ __launch_bounds__(256)
void pass2_kernel(float* __restrict__ out) {
    __shared__ __align__(16) float fac[PPB];

    const int b    = blockIdx.x >> 5;         // 32 blocks per batch
    const int k0   = (blockIdx.x & 31) * P2K;
    const int tile = k0 >> 8;                 // 256-code tiles (P2K=64 divides)
    const int tid  = threadIdx.x;

    for (int t = tid; t < PPB; t += 256) {
        int pix = b*PPB + t;
        float m0 = g_pixmax[pix],        m1 = g_pixmax[NPIX + pix];
        float s0 = g_pixsum[pix],        s1 = g_pixsum[NPIX + pix];
        float mf = fmaxf(m0, m1);
        float sf = s0*__expf(m0 - mf) + s1*__expf(m1 - mf);
        float mt = g_mtile[tile*NPIX + pix];
        fac[t] = __expf(mt - mf) * __frcp_rn(sf);
    }
    __syncthreads();

    const int w = tid >> 5, lane = tid & 31;
    const float4* f4p = reinterpret_cast<const float4*>(fac);

    #pragma unroll
    for (int kk = 0; kk < P2K/8; ++kk) {
        const int k = k0 + w*(P2K/8) + kk;
        float4* p = reinterpret_cast<float4*>(
            out + (size_t)BOWOFF + ((size_t)(b*NK + k))*PPB);
        float acc = 0.f;
        #pragma unroll 2
        for (int t = lane; t < PPB/4; t += 32) {
            float4 v  = __ldcs(p + t);
            float4 f4 = f4p[t];
            v.x *= f4.x; v.y *= f4.y; v.z *= f4.z; v.w *= f4.w;
            __stcs(p + t, v);
            acc += (v.x + v.y) + (v.z + v.w);
        }
        #pragma unroll
        for (int o = 16; o; o >>= 1) acc += __shfl_xor_sync(0xffffffffu, acc, o);
        if (lane == 0) g_bow[b*NK + k] = acc;
    }
}

// ---------------------------------------------------------------------------
// Pass 3: bow normalize (1024 threads, 2 codes/thread)
// ---------------------------------------------------------------------------
__global__ __launch_bounds__(1024)
void pass3_kernel(float* __restrict__ out) {
    __shared__ float redw[32];
    __shared__ float denom_s;
    const int b   = blockIdx.x;
    const int tid = threadIdx.x;
    const float invP = 1.0f / (float)PPB;

    float v0 = g_bow[b*NK + tid]        * invP;
    float v1 = g_bow[b*NK + tid + 1024] * invP;
    float acc = v0 + v1;
    #pragma unroll
    for (int o = 16; o; o >>= 1) acc += __shfl_xor_sync(0xffffffffu, acc, o);
    if ((tid & 31) == 0) redw[tid >> 5] = acc;
    __syncthreads();
    if (tid < 32) {
        float t = redw[tid];
        #pragma unroll
        for (int o = 16; o; o >>= 1) t += __shfl_xor_sync(0xffffffffu, t, o);
        if (tid == 0) denom_s = fmaxf(t, 1e-12f);
    }
    __syncthreads();
    const float inv = __frcp_rn(denom_s);
    out[b*NK + tid]        = v0 * inv;
    out[b*NK + tid + 1024] = v1 * inv;
}

// ---------------------------------------------------------------------------
extern "C" void kernel_launch(void* const* d_in, const int* in_sizes, int n_in,
                              void* d_out, int out_size) {
    const float* feat = (const float*)d_in[0];   // (32,256,30,30)
    const float* emb  = (const float*)d_in[1];   // (2048,256)
    const float* md   = (const float*)d_in[2];   // (1,)
    float* out = (float*)d_out;

    cudaFuncSetAttribute(pass1_kernel,
                         cudaFuncAttributeMaxDynamicSharedMemorySize, SMEM1_BYTES);

    prep_kernel <<<NK/2, 256>>>(emb);
    pass1_kernel<<<(NPIX/BM)*2, 256, SMEM1_BYTES>>>(feat, md, out);
    pass2_kernel<<<BB*NK/P2K, 256>>>(out);
    pass3_kernel<<<BB, 1024>>>(out);
    (void)in_sizes; (void)n_in; (void)out_size;
}